// round 6
// baseline (speedup 1.0000x reference)
#include <cuda_runtime.h>
#include <cuda_fp16.h>
#include <cstdint>

#define NB 2048
#define NROWS (NB + 2)
#define TPB 256
#define GRID_EDGE 740

__device__ double g_parts[1024];
__device__ unsigned int g_count = 0;
// Permuted, pair-duplicated fp16 LUT: row = 64 halves = 128B.
// Lane j (0..7) chunk: halves [8j .. 8j+8) = (P0,P1) for m = 4j .. 4j+3.
//   m <  8: P0 = ws[m]      (scalar coef), P1 = ws[16+m] (x S1)
//   m >= 8: vm=m-8, u=vm/3: P0 = ws[24+u], P1 = ws[8+u]  (x sh[vm%3], k3 folded)
__device__ __align__(16) __half g_LUTh[NROWS * 64];

// ---------------------------------------------------------------------------
// prep: full radial pipeline -> ws[32] per radius bin -> permuted fp16 rows.
// Rows NB, NB+1 are zero (r >= MAX_RADIUS).
// ---------------------------------------------------------------------------
__global__ void prep_kernel(const float* __restrict__ W1,
                            const float* __restrict__ W2) {
    __shared__ float sW2r[512];
    __shared__ float sW1[160];
    int tid = threadIdx.x;
    for (int q = tid; q < 512; q += blockDim.x) {
        int c = q >> 5, o = q & 31;
        const float* p = W2 + c * 256 + o * 8;
        float s = 0.f;
#pragma unroll
        for (int v = 0; v < 8; v++) s += p[v];
        sW2r[q] = s;
    }
    for (int q = tid; q < 160; q += blockDim.x) sW1[q] = W1[q];
    __syncthreads();

    int row = blockIdx.x * blockDim.x + tid;
    if (row >= NROWS) return;
    float ws[32];
#pragma unroll
    for (int o = 0; o < 32; o++) ws[o] = 0.f;
    if (row < NB) {
        float r = row * (3.0f / NB);
        float f[10];
#pragma unroll
        for (int k = 0; k < 10; k++) {
            float c = (k + 1) * (3.0f / 11.0f);
            float d = (r - c) * (11.0f / 3.0f);
            float den = 1.0f - d * d;
            f[k] = (den > 0.f) ? 1.14136f * __expf(2.0f - 2.0f / den) : 0.f;
        }
        float h[16];
#pragma unroll
        for (int c = 0; c < 16; c++) {
            float s = 0.f;
#pragma unroll
            for (int k = 0; k < 10; k++) s += f[k] * sW1[k * 16 + c];
            h[c] = fmaxf(s, 0.f) * 1.4142135623730951f;
        }
#pragma unroll
        for (int c = 0; c < 16; c++)
#pragma unroll
            for (int o = 0; o < 32; o++) ws[o] += h[c] * sW2r[c * 32 + o];
        const float GS = 0.015625f;  // 0.25 (1/sqrt(HID)) * 0.0625 (pw/sqrt(16))
        const float k3 = 0.5773502691896258f;
#pragma unroll
        for (int o = 0; o < 32; o++)
            ws[o] *= (o >= 8 && o < 16) ? GS * k3 : GS;
    }
    __half* dst = g_LUTh + row * 64;
#pragma unroll
    for (int j = 0; j < 8; j++) {
#pragma unroll
        for (int t = 0; t < 4; t++) {
            int m = 4 * j + t;
            float p0, p1;
            if (m < 8) { p0 = ws[m]; p1 = ws[16 + m]; }
            else { int u = (m - 8) / 3; p0 = ws[24 + u]; p1 = ws[8 + u]; }
            dst[8 * j + 2 * t + 0] = __float2half_rn(p0);
            dst[8 * j + 2 * t + 1] = __float2half_rn(p1);
        }
    }
}

__device__ __forceinline__ float2 h2f(unsigned int w) {
    __half2 h = *reinterpret_cast<__half2*>(&w);
    return __half22float2(h);
}

// ---------------------------------------------------------------------------
// edge kernel (persistent): 8 lanes per edge, 4 edges per warp. Per lane:
// 3 coalesced LDG.128 (LUT rowA chunk, rowB chunk, feature chunk) + lerp +
// 4-term dot. No smem tiles, no shuffles, no syncs in the hot loop.
// ---------------------------------------------------------------------------
__global__ void __launch_bounds__(TPB)
edge_kernel(const float* __restrict__ feat, const float* __restrict__ evec,
            const int* __restrict__ esrc, float* __restrict__ out,
            int E, int ntiles) {
    int tid = threadIdx.x;
    int lane = tid & 31;
    int wid = tid >> 5;
    int grp = lane >> 3;
    int j = lane & 7;
    const float SQ3 = 1.7320508075688772f;

    // static per-lane g-pattern select index: i0 = (j+1) % 3 (vector lanes)
    int i0 = (j + 1) % 3;
    bool scalar_lane = (j < 2);

    float facc = 0.f;

    for (int tile = blockIdx.x; tile < ntiles; tile += gridDim.x) {
        int e = tile * 32 + wid * 4 + grp;
        bool valid = e < E;
        int ec = valid ? e : 0;

        float ex = __ldg(evec + 3 * ec + 0);
        float ey = __ldg(evec + 3 * ec + 1);
        float ez = __ldg(evec + 3 * ec + 2);
        int idx = __ldg(esrc + ec);

        float r = sqrtf(ex * ex + ey * ey + ez * ez);
        float inv_r = 1.0f / r;
        float sh0 = SQ3 * ex * inv_r;
        float sh1 = SQ3 * ey * inv_r;
        float sh2 = SQ3 * ez * inv_r;
        float S1 = sh0 + sh1 + sh2;

        float t = fminf(r * (NB / 3.0f), (float)NB);
        int irow = (int)t;
        float frac = t - (float)irow;

        uint4 a4 = __ldg((const uint4*)g_LUTh + irow * 8 + j);
        uint4 b4 = __ldg((const uint4*)g_LUTh + (irow + 1) * 8 + j);
        float4 x4 = __ldg((const float4*)feat + (size_t)idx * 8 + j);

        // per-lane g multipliers (cyclic sh pattern for vector lanes)
        float ga = (i0 == 0) ? sh0 : ((i0 == 1) ? sh1 : sh2);
        float gb = (i0 == 0) ? sh1 : ((i0 == 1) ? sh2 : sh0);
        float gc = (i0 == 0) ? sh2 : ((i0 == 1) ? sh0 : sh1);
        float g0 = scalar_lane ? S1 : ga;
        float g1 = scalar_lane ? S1 : gb;
        float g2 = scalar_lane ? S1 : gc;
        float g3 = scalar_lane ? S1 : ga;

        if (valid) {
            const unsigned int* aw = (const unsigned int*)&a4;
            const unsigned int* bw = (const unsigned int*)&b4;
            float xv[4] = {x4.x, x4.y, x4.z, x4.w};
            float gv[4] = {g0, g1, g2, g3};
#pragma unroll
            for (int t4 = 0; t4 < 4; t4++) {
                float2 pa = h2f(aw[t4]);
                float2 pb = h2f(bw[t4]);
                float c0 = fmaf(frac, pb.x - pa.x, pa.x);
                float c1 = fmaf(frac, pb.y - pa.y, pa.y);
                facc = fmaf(xv[t4], fmaf(c1, gv[t4], c0), facc);
            }
        }
    }

    // ---- reduce: warp -> block -> g_parts; last block finishes ----
    __shared__ double sredd[TPB / 32];
    __shared__ int sflag;
#pragma unroll
    for (int off = 16; off > 0; off >>= 1)
        facc += __shfl_down_sync(0xffffffffu, facc, off);
    if (lane == 0) sredd[wid] = (double)facc;
    __syncthreads();
    if (tid == 0) {
        double b = 0.0;
#pragma unroll
        for (int w = 0; w < TPB / 32; w++) b += sredd[w];
        g_parts[blockIdx.x] = b;
        __threadfence();
        unsigned int prev = atomicAdd(&g_count, 1u);
        sflag = (prev == gridDim.x - 1) ? 1 : 0;
    }
    __syncthreads();
    if (sflag) {
        __threadfence();
        double s = 0.0;
        for (int i = tid; i < gridDim.x; i += TPB)
            s += ((volatile double*)g_parts)[i];
#pragma unroll
        for (int off = 16; off > 0; off >>= 1)
            s += __shfl_down_sync(0xffffffffu, s, off);
        __shared__ double fin[TPB / 32];
        if (lane == 0) fin[wid] = s;
        __syncthreads();
        if (tid == 0) {
            double v = 0.0;
#pragma unroll
            for (int w = 0; w < TPB / 32; w++) v += fin[w];
            out[0] = (float)v;
            g_count = 0;
        }
    }
}

extern "C" void kernel_launch(void* const* d_in, const int* in_sizes, int n_in,
                              void* d_out, int out_size) {
    const float* feat = (const float*)d_in[0];  // (N, 32)
    const float* evec = (const float*)d_in[1];  // (E, 3)
    const float* W1   = (const float*)d_in[2];  // (10, 16)
    const float* W2   = (const float*)d_in[3];  // (16, 256)
    const int*   esrc = (const int*)d_in[4];    // (E,)
    // edge_dst / num_nodes drop out: segment_sum then total sum == sum over
    // edges; the radial pipeline collapses to a 1-D LUT in r.
    int E = in_sizes[4];
    int ntiles = (E + 31) / 32;

    prep_kernel<<<(NROWS + 127) / 128, 128>>>(W1, W2);
    edge_kernel<<<GRID_EDGE, TPB>>>(feat, evec, esrc, (float*)d_out, E, ntiles);
}

// round 7
// speedup vs baseline: 1.0491x; 1.0491x over previous
#include <cuda_runtime.h>
#include <cstdint>

#define NB 2048
#define NROWS (NB + 2)
#define TPB 256
#define GRID_EDGE 1184

__device__ double g_parts[2048];
__device__ unsigned int g_count = 0;
// fp32 LUT, lane-major: row = 64 floats (256B).
// float index within row: h*32 + j*4 + tt*2 + {0,1}, where lane j owns
// elements m = 4j+t (t = 2h+tt), storing (P0, P1):
//   m <  8: P0 = ws[m],      P1 = ws[16+m]        (g = S1)
//   m >= 8: u=(m-8)/3:  P0 = ws[24+u], P1 = k3*ws[8+u]   (g = sh[(m-8)%3])
__device__ __align__(16) float g_LUTf[NROWS * 64];

// ---------------------------------------------------------------------------
// prep: full radial pipeline -> ws[32] per radius bin -> permuted fp32 rows.
// Rows NB, NB+1 are zero (r >= MAX_RADIUS).
// ---------------------------------------------------------------------------
__global__ void prep_kernel(const float* __restrict__ W1,
                            const float* __restrict__ W2) {
    __shared__ float sW2r[512];
    __shared__ float sW1[160];
    int tid = threadIdx.x;
    for (int q = tid; q < 512; q += blockDim.x) {
        int c = q >> 5, o = q & 31;
        const float* p = W2 + c * 256 + o * 8;
        float s = 0.f;
#pragma unroll
        for (int v = 0; v < 8; v++) s += p[v];
        sW2r[q] = s;
    }
    for (int q = tid; q < 160; q += blockDim.x) sW1[q] = W1[q];
    __syncthreads();

    int row = blockIdx.x * blockDim.x + tid;
    if (row >= NROWS) return;
    float ws[32];
#pragma unroll
    for (int o = 0; o < 32; o++) ws[o] = 0.f;
    if (row < NB) {
        float r = row * (3.0f / NB);
        float f[10];
#pragma unroll
        for (int k = 0; k < 10; k++) {
            float c = (k + 1) * (3.0f / 11.0f);
            float d = (r - c) * (11.0f / 3.0f);
            float den = 1.0f - d * d;
            f[k] = (den > 0.f) ? 1.14136f * __expf(2.0f - 2.0f / den) : 0.f;
        }
        float h[16];
#pragma unroll
        for (int c = 0; c < 16; c++) {
            float s = 0.f;
#pragma unroll
            for (int k = 0; k < 10; k++) s += f[k] * sW1[k * 16 + c];
            h[c] = fmaxf(s, 0.f) * 1.4142135623730951f;
        }
#pragma unroll
        for (int c = 0; c < 16; c++)
#pragma unroll
            for (int o = 0; o < 32; o++) ws[o] += h[c] * sW2r[c * 32 + o];
        const float GS = 0.015625f;  // 0.25 (1/sqrt(HID)) * 0.0625 (pw/sqrt(16))
        const float k3 = 0.5773502691896258f;
#pragma unroll
        for (int o = 0; o < 32; o++)
            ws[o] *= (o >= 8 && o < 16) ? GS * k3 : GS;
    }
    float* dst = g_LUTf + row * 64;
#pragma unroll
    for (int j = 0; j < 8; j++) {
#pragma unroll
        for (int t = 0; t < 4; t++) {
            int m = 4 * j + t;
            float p0, p1;
            if (m < 8) { p0 = ws[m]; p1 = ws[16 + m]; }
            else { int u = (m - 8) / 3; p0 = ws[24 + u]; p1 = ws[8 + u]; }
            int h = t >> 1, tt = t & 1;
            dst[h * 32 + j * 4 + tt * 2 + 0] = p0;
            dst[h * 32 + j * 4 + tt * 2 + 1] = p1;
        }
    }
}

// ---------------------------------------------------------------------------
// edge kernel (persistent): 8 lanes per edge, 4 edges per warp. Per lane:
// 5 coalesced LDG.128 (2 LUT chunks x rows irow/irow+1, 1 feature chunk),
// fp32 lerp + 4-term dot. No smem tiles, no shuffles, no hot-loop syncs.
// ---------------------------------------------------------------------------
__global__ void __launch_bounds__(TPB)
edge_kernel(const float* __restrict__ feat, const float* __restrict__ evec,
            const int* __restrict__ esrc, float* __restrict__ out,
            int E, int ntiles) {
    int tid = threadIdx.x;
    int lane = tid & 31;
    int wid = tid >> 5;
    int grp = lane >> 3;
    int j = lane & 7;
    const float SQ3 = 1.7320508075688772f;

    // loop-invariant lane predicates for the g-select
    int i0 = (j + 1) % 3;
    bool scalar_lane = (j < 2);
    bool pA = (i0 == 0), pB = (i0 == 1);

    float facc = 0.f;

    for (int tile = blockIdx.x; tile < ntiles; tile += gridDim.x) {
        int e = tile * 32 + wid * 4 + grp;
        bool valid = e < E;
        int ec = valid ? e : 0;

        float ex = __ldg(evec + 3 * ec + 0);
        float ey = __ldg(evec + 3 * ec + 1);
        float ez = __ldg(evec + 3 * ec + 2);
        int idx = __ldg(esrc + ec);

        float r = sqrtf(ex * ex + ey * ey + ez * ez);
        float inv_r = 1.0f / r;
        float sh0 = SQ3 * ex * inv_r;
        float sh1 = SQ3 * ey * inv_r;
        float sh2 = SQ3 * ez * inv_r;
        float S1 = sh0 + sh1 + sh2;

        float t = fminf(r * (NB / 3.0f), (float)NB);
        int irow = (int)t;
        float frac = t - (float)irow;

        const float4* base = (const float4*)(g_LUTf + irow * 64) + j;
        float4 a0 = __ldg(base);          // row irow, pairs t=0,1
        float4 a1 = __ldg(base + 8);      // row irow, pairs t=2,3
        float4 b0 = __ldg(base + 16);     // row irow+1, pairs t=0,1
        float4 b1 = __ldg(base + 24);     // row irow+1, pairs t=2,3
        float4 x4 = __ldg((const float4*)feat + (size_t)idx * 8 + j);

        // per-lane g multipliers (cyclic sh pattern for vector lanes)
        float ga = pA ? sh0 : (pB ? sh1 : sh2);
        float gb = pA ? sh1 : (pB ? sh2 : sh0);
        float gc = pA ? sh2 : (pB ? sh0 : sh1);
        float g0 = scalar_lane ? S1 : ga;
        float g1 = scalar_lane ? S1 : gb;
        float g2 = scalar_lane ? S1 : gc;
        float g3 = scalar_lane ? S1 : ga;

        if (valid) {
            float c0, c1;
            c0 = fmaf(frac, b0.x - a0.x, a0.x);
            c1 = fmaf(frac, b0.y - a0.y, a0.y);
            facc = fmaf(x4.x, fmaf(c1, g0, c0), facc);
            c0 = fmaf(frac, b0.z - a0.z, a0.z);
            c1 = fmaf(frac, b0.w - a0.w, a0.w);
            facc = fmaf(x4.y, fmaf(c1, g1, c0), facc);
            c0 = fmaf(frac, b1.x - a1.x, a1.x);
            c1 = fmaf(frac, b1.y - a1.y, a1.y);
            facc = fmaf(x4.z, fmaf(c1, g2, c0), facc);
            c0 = fmaf(frac, b1.z - a1.z, a1.z);
            c1 = fmaf(frac, b1.w - a1.w, a1.w);
            facc = fmaf(x4.w, fmaf(c1, g3, c0), facc);
        }
    }

    // ---- reduce: warp -> block -> g_parts; last block finishes ----
    __shared__ double sredd[TPB / 32];
    __shared__ int sflag;
#pragma unroll
    for (int off = 16; off > 0; off >>= 1)
        facc += __shfl_down_sync(0xffffffffu, facc, off);
    if (lane == 0) sredd[wid] = (double)facc;
    __syncthreads();
    if (tid == 0) {
        double b = 0.0;
#pragma unroll
        for (int w = 0; w < TPB / 32; w++) b += sredd[w];
        g_parts[blockIdx.x] = b;
        __threadfence();
        unsigned int prev = atomicAdd(&g_count, 1u);
        sflag = (prev == gridDim.x - 1) ? 1 : 0;
    }
    __syncthreads();
    if (sflag) {
        __threadfence();
        double s = 0.0;
        for (int i = tid; i < gridDim.x; i += TPB)
            s += ((volatile double*)g_parts)[i];
#pragma unroll
        for (int off = 16; off > 0; off >>= 1)
            s += __shfl_down_sync(0xffffffffu, s, off);
        __shared__ double fin[TPB / 32];
        if (lane == 0) fin[wid] = s;
        __syncthreads();
        if (tid == 0) {
            double v = 0.0;
#pragma unroll
            for (int w = 0; w < TPB / 32; w++) v += fin[w];
            out[0] = (float)v;
            g_count = 0;
        }
    }
}

extern "C" void kernel_launch(void* const* d_in, const int* in_sizes, int n_in,
                              void* d_out, int out_size) {
    const float* feat = (const float*)d_in[0];  // (N, 32)
    const float* evec = (const float*)d_in[1];  // (E, 3)
    const float* W1   = (const float*)d_in[2];  // (10, 16)
    const float* W2   = (const float*)d_in[3];  // (16, 256)
    const int*   esrc = (const int*)d_in[4];    // (E,)
    // edge_dst / num_nodes drop out: segment_sum then total sum == sum over
    // edges; the radial pipeline collapses to a 1-D LUT in r.
    int E = in_sizes[4];
    int ntiles = (E + 31) / 32;

    prep_kernel<<<(NROWS + 127) / 128, 128>>>(W1, W2);
    edge_kernel<<<GRID_EDGE, TPB>>>(feat, evec, esrc, (float*)d_out, E, ntiles);
}

// round 8
// speedup vs baseline: 1.0556x; 1.0062x over previous
#include <cuda_runtime.h>
#include <cstdint>

#define NB 2048
#define NROWS (NB + 2)
#define TPB 256
#define NBLK 1036            // 7 blocks/SM x 148 SMs — all co-resident

__device__ double g_parts[2048];
__device__ unsigned int g_count = 0;
__device__ unsigned int g_bar = 0;
// LUT row = 128 floats (512B): [0:64) permuted (P0,P1) values, [64:128) slopes
// (next row - this row). Value index: h*32 + j*4 + tt*2 + {0,1} for element
// m = 4j + (2h+tt) owned by lane j:
//   m <  8: P0 = ws[m],  P1 = ws[16+m]          (g = S1)
//   m >= 8: u=(m-8)/3: P0 = ws[24+u], P1 = k3*ws[8+u]  (g = sh[(m-8)%3])
__device__ __align__(16) float g_LUT[NROWS * 128];

__global__ void __launch_bounds__(TPB, 7)
fused_kernel(const float* __restrict__ feat, const float* __restrict__ evec,
             const int* __restrict__ esrc, const float* __restrict__ W1,
             const float* __restrict__ W2, float* __restrict__ out,
             int E, int ntiles) {
    __shared__ float sW1[160];
    __shared__ float sW2r[512];
    __shared__ float sP[3][64];
    __shared__ double sredd[TPB / 32];
    __shared__ int sflag;

    int tid = threadIdx.x;
    int lane = tid & 31;
    int wid = tid >> 5;
    int bid = blockIdx.x;

    // ================= phase 1: build LUT (blocks 0..1024) =================
    if (bid < (NROWS + 1) / 2) {
        // stage W1 and W2 reduced over trailing v'
        for (int q = tid; q < 512; q += TPB) {
            int c = q >> 5, o = q & 31;
            const float4* p = (const float4*)(W2 + c * 256 + o * 8);
            float4 u0 = __ldg(p), u1 = __ldg(p + 1);
            sW2r[q] = u0.x + u0.y + u0.z + u0.w + u1.x + u1.y + u1.z + u1.w;
        }
        for (int q = tid; q < 160; q += TPB) sW1[q] = W1[q];
        __syncthreads();

        // rows 2b, 2b+1 (+ 2b+2 for slope); thread t<96: (row_off, m)
        if (tid < 96) {
            int ro = tid >> 5;
            int m = tid & 31;
            int rw = 2 * bid + ro;
            float P0 = 0.f, P1 = 0.f;
            if (rw < NB) {
                float r = rw * (3.0f / NB);
                float f[10];
#pragma unroll
                for (int k = 0; k < 10; k++) {
                    float c = (k + 1) * (3.0f / 11.0f);
                    float d = (r - c) * (11.0f / 3.0f);
                    float den = 1.0f - d * d;
                    f[k] = (den > 0.f) ? 1.14136f * __expf(2.0f - 2.0f / den)
                                       : 0.f;
                }
                float h[16];
#pragma unroll
                for (int c = 0; c < 16; c++) {
                    float s = 0.f;
#pragma unroll
                    for (int k = 0; k < 10; k++) s += f[k] * sW1[k * 16 + c];
                    h[c] = fmaxf(s, 0.f) * 1.4142135623730951f;
                }
                const float GS = 0.015625f;  // 0.25/sqrt(HID) * pw/sqrt(16)
                const float k3 = 0.5773502691896258f;
                int o0, o1;
                float sc1;
                if (m < 8) { o0 = m; o1 = 16 + m; sc1 = GS; }
                else { int u = (m - 8) / 3; o0 = 24 + u; o1 = 8 + u; sc1 = GS * k3; }
#pragma unroll
                for (int c = 0; c < 16; c++) {
                    P0 += h[c] * sW2r[c * 32 + o0];
                    P1 += h[c] * sW2r[c * 32 + o1];
                }
                P0 *= GS;
                P1 *= sc1;
            }
            int j = m >> 2, tm = m & 3, hh = tm >> 1, tt = tm & 1;
            int pos = hh * 32 + 4 * j + 2 * tt;
            sP[ro][pos] = P0;
            sP[ro][pos + 1] = P1;
        }
        __syncthreads();

        // write value + slope rows
        if (tid < 128) {
            int ro = tid >> 6;
            int idx = tid & 63;
            int rw = 2 * bid + ro;
            if (rw < NROWS) {
                float v = sP[ro][idx];
                g_LUT[rw * 128 + idx] = v;
                g_LUT[rw * 128 + 64 + idx] = sP[ro + 1][idx] - v;
            }
        }
    }

    // ================= grid-wide barrier =================
    __threadfence();
    __syncthreads();
    if (tid == 0) {
        atomicAdd(&g_bar, 1u);
        while (*(volatile unsigned int*)&g_bar < (unsigned int)gridDim.x)
            __nanosleep(64);
    }
    __syncthreads();
    __threadfence();

    // ================= phase 2: edge loop =================
    int grp = lane >> 3;
    int j = lane & 7;
    const float SQ3 = 1.7320508075688772f;
    int i0 = (j + 1) % 3;
    bool scalar_lane = (j < 2);
    bool pA = (i0 == 0), pB = (i0 == 1);

    float facc = 0.f;

    for (int tile = bid; tile < ntiles; tile += gridDim.x) {
        int e = tile * 32 + wid * 4 + grp;
        bool valid = e < E;
        int ec = valid ? e : 0;

        float ex = __ldg(evec + 3 * ec + 0);
        float ey = __ldg(evec + 3 * ec + 1);
        float ez = __ldg(evec + 3 * ec + 2);
        int idx = __ldg(esrc + ec);

        float d2 = fmaf(ex, ex, fmaf(ey, ey, ez * ez));
        float inv_r = rsqrtf(d2);
        float r = d2 * inv_r;
        float sh0 = SQ3 * ex * inv_r;
        float sh1 = SQ3 * ey * inv_r;
        float sh2 = SQ3 * ez * inv_r;
        float S1 = sh0 + sh1 + sh2;

        float t = fminf(r * (NB / 3.0f), (float)NB);
        int irow = (int)t;
        float frac = t - (float)irow;

        const float4* base = (const float4*)g_LUT + irow * 32 + j;
        float4 v0 = __ldg(base);       // values t=0,1
        float4 v1 = __ldg(base + 8);   // values t=2,3
        float4 s0 = __ldg(base + 16);  // slopes t=0,1
        float4 s1 = __ldg(base + 24);  // slopes t=2,3
        float4 x4 = __ldg((const float4*)feat + (size_t)idx * 8 + j);

        float ga = pA ? sh0 : (pB ? sh1 : sh2);
        float gb = pA ? sh1 : (pB ? sh2 : sh0);
        float gc = pA ? sh2 : (pB ? sh0 : sh1);
        float g0 = scalar_lane ? S1 : ga;
        float g1 = scalar_lane ? S1 : gb;
        float g2 = scalar_lane ? S1 : gc;
        float g3 = scalar_lane ? S1 : ga;

        if (valid) {
            float c0, c1;
            c0 = fmaf(frac, s0.x, v0.x);
            c1 = fmaf(frac, s0.y, v0.y);
            facc = fmaf(x4.x, fmaf(c1, g0, c0), facc);
            c0 = fmaf(frac, s0.z, v0.z);
            c1 = fmaf(frac, s0.w, v0.w);
            facc = fmaf(x4.y, fmaf(c1, g1, c0), facc);
            c0 = fmaf(frac, s1.x, v1.x);
            c1 = fmaf(frac, s1.y, v1.y);
            facc = fmaf(x4.z, fmaf(c1, g2, c0), facc);
            c0 = fmaf(frac, s1.z, v1.z);
            c1 = fmaf(frac, s1.w, v1.w);
            facc = fmaf(x4.w, fmaf(c1, g3, c0), facc);
        }
    }

    // ================= reduce + fused finish =================
#pragma unroll
    for (int off = 16; off > 0; off >>= 1)
        facc += __shfl_down_sync(0xffffffffu, facc, off);
    if (lane == 0) sredd[wid] = (double)facc;
    __syncthreads();
    if (tid == 0) {
        double b = 0.0;
#pragma unroll
        for (int w = 0; w < TPB / 32; w++) b += sredd[w];
        g_parts[bid] = b;
        __threadfence();
        unsigned int prev = atomicAdd(&g_count, 1u);
        sflag = (prev == gridDim.x - 1) ? 1 : 0;
    }
    __syncthreads();
    if (sflag) {
        __threadfence();
        double s = 0.0;
        for (int i = tid; i < gridDim.x; i += TPB)
            s += ((volatile double*)g_parts)[i];
#pragma unroll
        for (int off = 16; off > 0; off >>= 1)
            s += __shfl_down_sync(0xffffffffu, s, off);
        __shared__ double fin[TPB / 32];
        if (lane == 0) fin[wid] = s;
        __syncthreads();
        if (tid == 0) {
            double v = 0.0;
#pragma unroll
            for (int w = 0; w < TPB / 32; w++) v += fin[w];
            out[0] = (float)v;
            g_count = 0;
            g_bar = 0;
        }
    }
}

extern "C" void kernel_launch(void* const* d_in, const int* in_sizes, int n_in,
                              void* d_out, int out_size) {
    const float* feat = (const float*)d_in[0];  // (N, 32)
    const float* evec = (const float*)d_in[1];  // (E, 3)
    const float* W1   = (const float*)d_in[2];  // (10, 16)
    const float* W2   = (const float*)d_in[3];  // (16, 256)
    const int*   esrc = (const int*)d_in[4];    // (E,)
    // edge_dst / num_nodes drop out: segment_sum then total sum == sum over
    // edges; radial pipeline collapses to a 1-D (value, slope) LUT in r.
    int E = in_sizes[4];
    int ntiles = (E + 31) / 32;

    fused_kernel<<<NBLK, TPB>>>(feat, evec, esrc, W1, W2, (float*)d_out, E,
                                ntiles);
}